// round 7
// baseline (speedup 1.0000x reference)
#include <cuda_runtime.h>
#include <math.h>
#include <stdint.h>

#define Tt 8192
#define Kk 64
#define NBLK 512            // pipeline blocks
#define TPB 128             // timesteps per block
#define SEQB 64             // pipeline blocks per sequence
#define NSEQ 8
#define NTH 512             // threads per block

// ---- device scratch (static; no runtime alloc allowed) ----
__device__ float4 g_agg[NBLK*Kk];      // per-block scan aggregate (A, Z)
__device__ float2 g_pre[NBLK*Kk];      // per-block entering prefix
__device__ float4 g_sG[NSEQ*8*Kk];     // combiner group summaries
__device__ float2 g_sE[NSEQ*8*Kk];     // combiner group entry states
__device__ int    g_bst[NBLK];         // aggregate-published flags
__device__ int    g_pflag[NSEQ];       // prefixes-published flags
__device__ int    g_sflag;             // sigma ready
__device__ float  g_sigma_inv;

__device__ __forceinline__ float softplusf(float x){
    return (x > 20.f) ? x : log1pf(expf(x));
}

// -------- init: reset flags (runs every launch; graph-safe) ----------------
__global__ void k_init()
{
    int t = threadIdx.x;
    if (t < NBLK) g_bst[t] = 0;
    if (t < NSEQ) g_pflag[t] = 0;
    if (t == 0)   g_sflag = 0;
}

// ============================ fused kernel ==================================
// block 0: sigma (Gram -> 6 squarings -> 8 power iters -> Rayleigh)
// blocks 1..512: GEMM + pointwise + chunked scan (sequence combiner) + output
__global__ void __launch_bounds__(NTH, 2)
k_fused(const float* __restrict__ x,
        const float* __restrict__ dt,
        const float* __restrict__ alpha_mod,
        const float* __restrict__ omega_mod,
        const float* __restrict__ tau_mod,
        const float* __restrict__ bvec,
        const float* __restrict__ W,
        const float* __restrict__ s_real_raw,
        const float* __restrict__ s_imag,
        const float* __restrict__ tau_raw,
        float* __restrict__ out)
{
    extern __shared__ float sm[];
    int tid = threadIdx.x;   // 512

    if (blockIdx.x == 0) {
        // ------------------------- sigma block ------------------------------
        float* sW = sm;               // 64 x 132
        float* M  = sm + 64*132;      // 64 x 68
        float* H  = sm + 64*132 + 64*68;
        __shared__ float vbuf[2][64];
        __shared__ float red[64];
        __shared__ float red2[64];

        const float4* W4 = (const float4*)W;    // 2048 float4
        #pragma unroll
        for (int r = 0; r < 4; ++r) {
            int lin = tid + r*NTH;
            int k = lin >> 5, d4 = lin & 31;
            ((float4*)&sW[k*132])[d4] = W4[lin];
        }
        __syncthreads();

        int ti = tid >> 4, tj = tid & 15;       // valid for tid<256
        if (tid < 256) {   // Gram
            float acc[4][4];
            #pragma unroll
            for (int a=0;a<4;a++){
                #pragma unroll
                for (int b2=0;b2<4;b2++) acc[a][b2]=0.f;
            }
            #pragma unroll 4
            for (int d4 = 0; d4 < 32; ++d4) {
                float4 av[4], bv[4];
                #pragma unroll
                for (int a=0;a<4;a++)  av[a] = ((const float4*)&sW[(ti*4+a)*132])[d4];
                #pragma unroll
                for (int b2=0;b2<4;b2++) bv[b2] = ((const float4*)&sW[(tj*4+b2)*132])[d4];
                #pragma unroll
                for (int a=0;a<4;a++){
                    #pragma unroll
                    for (int b2=0;b2<4;b2++){
                        acc[a][b2] += av[a].x*bv[b2].x + av[a].y*bv[b2].y
                                    + av[a].z*bv[b2].z + av[a].w*bv[b2].w;
                    }
                }
            }
            #pragma unroll
            for (int a=0;a<4;a++){
                #pragma unroll
                for (int b2=0;b2<4;b2++)
                    M[(ti*4+a)*68 + (tj*4+b2)] = acc[a][b2];
            }
        }
        __syncthreads();

        float* cur = M; float* oth = H;
        for (int sq = 0; sq < 6; ++sq) {
            if (tid < 256) {
                float acc[4][4];
                #pragma unroll
                for (int a=0;a<4;a++){
                    #pragma unroll
                    for (int b2=0;b2<4;b2++) acc[a][b2]=0.f;
                }
                #pragma unroll 4
                for (int l = 0; l < 64; ++l) {
                    float a0 = cur[(ti*4+0)*68 + l];
                    float a1 = cur[(ti*4+1)*68 + l];
                    float a2 = cur[(ti*4+2)*68 + l];
                    float a3 = cur[(ti*4+3)*68 + l];
                    float4 bv = *(const float4*)&cur[l*68 + tj*4];
                    acc[0][0]+=a0*bv.x; acc[0][1]+=a0*bv.y; acc[0][2]+=a0*bv.z; acc[0][3]+=a0*bv.w;
                    acc[1][0]+=a1*bv.x; acc[1][1]+=a1*bv.y; acc[1][2]+=a1*bv.z; acc[1][3]+=a1*bv.w;
                    acc[2][0]+=a2*bv.x; acc[2][1]+=a2*bv.y; acc[2][2]+=a2*bv.z; acc[2][3]+=a2*bv.w;
                    acc[3][0]+=a3*bv.x; acc[3][1]+=a3*bv.y; acc[3][2]+=a3*bv.z; acc[3][3]+=a3*bv.w;
                }
                #pragma unroll
                for (int a=0;a<4;a++){
                    #pragma unroll
                    for (int b2=0;b2<4;b2++)
                        oth[(ti*4+a)*68 + tj*4+b2] = acc[a][b2];
                }
            }
            __syncthreads();
            if (tid < 64) red[tid] = oth[tid*68 + tid];
            __syncthreads();
            for (int s = 32; s > 0; s >>= 1) {
                if (tid < s) red[tid] += red[tid+s];
                __syncthreads();
            }
            float sc = 1.0f / red[0];
            #pragma unroll
            for (int r = 0; r < 8; ++r) {
                int lin = tid + r*NTH;
                oth[(lin>>6)*68 + (lin&63)] *= sc;
            }
            __syncthreads();
            float* t = cur; cur = oth; oth = t;
        }
        if (tid < 64) vbuf[0][tid] = 1.0f + 0.001f*(float)tid;
        __syncthreads();
        int i = tid >> 2, p4 = tid & 3;
        for (int it = 0; it < 8; ++it) {
            if (tid < 256) {
                const float* v = vbuf[it & 1];
                float s = 0.f;
                #pragma unroll
                for (int l4 = 0; l4 < 4; ++l4) {
                    int lb = p4*16 + l4*4;
                    float4 m = *(const float4*)&cur[i*68 + lb];
                    s += m.x*v[lb] + m.y*v[lb+1] + m.z*v[lb+2] + m.w*v[lb+3];
                }
                s += __shfl_xor_sync(0xffffffffu, s, 1);
                s += __shfl_xor_sync(0xffffffffu, s, 2);
                if (p4 == 0) vbuf[(it+1)&1][i] = s;
            }
            __syncthreads();
            if ((it & 3) == 3) {
                float* vn = vbuf[(it+1)&1];
                if (tid < 64) red[tid] = vn[tid]*vn[tid];
                __syncthreads();
                for (int st = 32; st > 0; st >>= 1) {
                    if (tid < st) red[tid] += red[tid+st];
                    __syncthreads();
                }
                float scl = rsqrtf(red[0]);
                if (tid < 64) vn[tid] *= scl;
                __syncthreads();
            }
        }
        const float* vf = vbuf[0];
        float* tvec = oth;
        if (tid < 128) {
            float s = 0.f;
            #pragma unroll 4
            for (int kk = 0; kk < 64; ++kk) s += sW[kk*132 + tid] * vf[kk];
            tvec[tid] = s;
        }
        __syncthreads();
        if (tid < 64) {
            float s = 0.f;
            #pragma unroll 4
            for (int d = 0; d < 128; ++d) s += sW[tid*132 + d] * tvec[d];
            red[tid]  = s * vf[tid];
            red2[tid] = vf[tid]*vf[tid];
        }
        __syncthreads();
        for (int st = 32; st > 0; st >>= 1) {
            if (tid < st) { red[tid] += red[tid+st]; red2[tid] += red2[tid+st]; }
            __syncthreads();
        }
        if (tid == 0) {
            g_sigma_inv = rsqrtf(red[0] / red2[0]);
            __threadfence();
            atomicExch(&g_sflag, 1);
        }
        return;
    }

    // ------------------------- pipeline blocks ------------------------------
    __shared__ float4 sSum[8*64];     // per-sub-chunk summaries (8 chunks of 16)
    __shared__ float2 sPre[64];       // per-lane prefix entering this block
    __shared__ float  sA0[64];        // alpha0[k]
    __shared__ float  sO0[64];        // omega0[k]

    int lin = blockIdx.x - 1;         // 0..511
    int seq = lin >> 6;
    int p   = lin & (SEQB-1);
    int bt0 = lin * TPB;

    float* xs = sm;                   // 128 rows x stride 132
    float* ws = sm + 128*132;         // 64 rows x stride 132 (raw W)

    const float4* Wg4 = (const float4*)W;
    #pragma unroll
    for (int r = 0; r < 4; ++r) {
        int l = tid + r*NTH;
        int k2 = l >> 5, d4 = l & 31;
        ((float4*)&ws[k2*132])[d4] = Wg4[l];
    }
    const float4* xg4 = (const float4*)x + (size_t)bt0*32;
    #pragma unroll
    for (int r = 0; r < 8; ++r) {
        int l = tid + r*NTH;
        int i2 = l >> 5, d4 = l & 31;
        ((float4*)&xs[i2*132])[d4] = xg4[l];
    }
    __syncthreads();

    // --- fp32 GEMM: 512 threads, 2 rows x 8 cols each ---
    int kq = tid & 7, bq = tid >> 3;  // kq: 8 k-groups, bq: 64 row-pairs
    float acc[2][8];
    #pragma unroll
    for (int a=0;a<2;a++){
        #pragma unroll
        for (int j=0;j<8;j++) acc[a][j]=0.f;
    }
    #pragma unroll 4
    for (int d4 = 0; d4 < 32; ++d4) {
        float4 xa[2];
        #pragma unroll
        for (int a=0;a<2;a++) xa[a] = ((const float4*)&xs[(bq*2+a)*132])[d4];
        #pragma unroll
        for (int jh = 0; jh < 2; ++jh) {
            float4 wb[4];
            #pragma unroll
            for (int j=0;j<4;j++) wb[j] = ((const float4*)&ws[(kq+8*(jh*4+j))*132])[d4];
            #pragma unroll
            for (int a=0;a<2;a++){
                #pragma unroll
                for (int j=0;j<4;j++){
                    acc[a][jh*4+j] += xa[a].x*wb[j].x + xa[a].y*wb[j].y
                                    + xa[a].z*wb[j].z + xa[a].w*wb[j].w;
                }
            }
        }
    }

    // alpha0/omega0 once per block (64 softplus instead of 4096)
    if (tid < 64) {
        float tauv = softplusf(tau_raw[0]) + 1e-3f;
        sA0[tid] = (softplusf(s_real_raw[tid]) + 1e-6f) * tauv;
        sO0[tid] = s_imag[tid] * tauv;
    }
    __syncthreads();   // tiles consumed; reuse as a/u stage

    float* sAr = sm;                  // [128][65]
    float* sAi = sm + 128*65;
    float* sU  = sm + 2*128*65;

    // --- epilogue: a_t via tiny-arg Taylor; store raw acc (sigma later) ---
    #pragma unroll
    for (int a = 0; a < 2; ++a) {
        int tl = bq*2 + a;            // local t in [0,128)
        int bt = bt0 + tl;
        float dtv = dt[bt];
        float tm  = tau_mod[bt];
        #pragma unroll
        for (int j = 0; j < 8; ++j) {
            int k2 = kq + 8*j;
            int idx = bt*64 + k2;
            float ad = sA0[k2] * __expf(alpha_mod[idx] + tm) * dtv;
            float th = sO0[k2] * __expf(omega_mod[idx] + tm) * dtv;
            float rho = 1.f - ad*(1.f - ad*(0.5f - 0.16666667f*ad));
            float t2  = th*th;
            float cs  = 1.f - 0.5f*t2*(1.f - 0.083333336f*t2);
            float sn  = th*(1.f - 0.16666667f*t2);
            sAr[tl*65 + k2] = rho*cs;
            sAi[tl*65 + k2] = rho*sn;
            sU [tl*65 + k2] = acc[a][j];
        }
    }

    // --- wait for sigma (fully overlapped by the GEMM/epilogue above) ---
    if (tid == 0) {
        while (atomicAdd(&g_sflag, 0) == 0) __nanosleep(100);
    }
    __syncthreads();
    __threadfence();
    float siginv = *(volatile float*)&g_sigma_inv;

    int cc = tid >> 6, k = tid & 63;  // 8 sub-chunks x 64 lanes
    float bk = bvec[k];

    // --- local sub-chunk scans: 8 x 16 steps ---
    {
        int tb = cc*16;
        float zr=0.f, zi=0.f, Ar=1.f, Ai=0.f;
        #pragma unroll 8
        for (int i = 0; i < 16; ++i) {
            float ar = sAr[(tb+i)*65 + k];
            float ai = sAi[(tb+i)*65 + k];
            float u  = siginv*sU[(tb+i)*65 + k] + bk;
            float nr = ar*zr - ai*zi + u;
            float ni = ai*zr + ar*zi;
            zr = nr; zi = ni;
            float br = ar*Ar - ai*Ai;
            float bi = ai*Ar + ar*Ai;
            Ar = br; Ai = bi;
        }
        sSum[cc*64 + k] = make_float4(Ar, Ai, zr, zi);
    }
    __syncthreads();

    // --- block aggregate (lanes 0..63), publish ---
    if (tid < 64) {
        float bAr=1.f, bAi=0.f, bZr=0.f, bZi=0.f;
        #pragma unroll
        for (int j = 0; j < 8; ++j) {
            float4 s4 = sSum[j*64 + tid];
            float nzr = s4.x*bZr - s4.y*bZi + s4.z;
            float nzi = s4.y*bZr + s4.x*bZi + s4.w;
            float nar = s4.x*bAr - s4.y*bAi;
            float nai = s4.y*bAr + s4.x*bAi;
            bZr=nzr; bZi=nzi; bAr=nar; bAi=nai;
        }
        g_agg[lin*Kk + tid] = make_float4(bAr, bAi, bZr, bZi);
    }
    __threadfence();
    __syncthreads();

    float pr = 0.f, pi = 0.f;
    if (p == 0) {
        // -------- combiner: compute all 64 prefixes for this sequence -------
        if (tid == 0) atomicExch(&g_bst[lin], 1);   // own agg published
        if (tid > 0 && tid < 64) {
            while (atomicAdd(&g_bst[lin + tid], 0) == 0) __nanosleep(80);
        }
        __syncthreads();
        __threadfence();
        int g = tid >> 6;   // group 0..7 (8 chunks each)
        {   // step1: group summaries
            float GA=1.f, GAi=0.f, GZ=0.f, GZi=0.f;
            #pragma unroll
            for (int c = 0; c < 8; ++c) {
                float4 ag = __ldcg(&g_agg[(lin + g*8 + c)*Kk + k]);
                float nz  = ag.x*GZ - ag.y*GZi + ag.z;
                float nzi = ag.y*GZ + ag.x*GZi + ag.w;
                float na  = ag.x*GA - ag.y*GAi;
                float nai = ag.y*GA + ag.x*GAi;
                GZ=nz; GZi=nzi; GA=na; GAi=nai;
            }
            g_sG[(seq*8 + g)*Kk + k] = make_float4(GA, GAi, GZ, GZi);
        }
        __threadfence();
        __syncthreads();
        // step2: group entry states (serial over 8 groups, 64 threads)
        if (tid < 64) {
            float zr2 = 0.f, zi2 = 0.f;
            #pragma unroll
            for (int g2 = 0; g2 < 8; ++g2) {
                g_sE[(seq*8 + g2)*Kk + tid] = make_float2(zr2, zi2);
                float4 f4 = g_sG[(seq*8 + g2)*Kk + tid];
                float nz  = f4.x*zr2 - f4.y*zi2 + f4.z;
                float nzi = f4.y*zr2 + f4.x*zi2 + f4.w;
                zr2 = nz; zi2 = nzi;
            }
        }
        __threadfence();
        __syncthreads();
        {   // step3: per-chunk prefixes
            float2 e = g_sE[(seq*8 + g)*Kk + k];
            float zr2 = e.x, zi2 = e.y;
            #pragma unroll
            for (int c = 0; c < 8; ++c) {
                g_pre[(lin + g*8 + c)*Kk + k] = make_float2(zr2, zi2);
                float4 ag = __ldcg(&g_agg[(lin + g*8 + c)*Kk + k]);
                float nz  = ag.x*zr2 - ag.y*zi2 + ag.z;
                float nzi = ag.y*zr2 + ag.x*zi2 + ag.w;
                zr2 = nz; zi2 = nzi;
            }
        }
        __threadfence();
        __syncthreads();
        if (tid == 0) atomicExch(&g_pflag[seq], 1);
        // own prefix stays zero
    } else {
        if (tid == 0) {
            atomicExch(&g_bst[lin], 1);
            while (atomicAdd(&g_pflag[seq], 0) == 0) __nanosleep(100);
        }
        __syncthreads();
        __threadfence();
        if (tid < 64) {
            float2 pz = __ldcg(&g_pre[lin*Kk + tid]);
            pr = pz.x; pi = pz.y;
        }
    }

    if (tid < 64) sPre[tid] = make_float2(pr, pi);
    __syncthreads();

    // --- final scan with correct init, write output ---
    {
        float2 z0 = sPre[k];
        float zr = z0.x, zi = z0.y;
        #pragma unroll
        for (int j = 0; j < 7; ++j) {
            if (j < cc) {
                float4 s4 = sSum[j*64 + k];
                float nr = s4.x*zr - s4.y*zi + s4.z;
                float ni = s4.y*zr + s4.x*zi + s4.w;
                zr = nr; zi = ni;
            }
        }
        int tb = cc*16;
        float* outb = out + (size_t)(bt0 + tb)*128;
        #pragma unroll 8
        for (int i = 0; i < 16; ++i) {
            float ar = sAr[(tb+i)*65 + k];
            float ai = sAi[(tb+i)*65 + k];
            float u  = siginv*sU[(tb+i)*65 + k] + bk;
            float nr = ar*zr - ai*zi + u;
            float ni = ai*zr + ar*zi;
            zr = nr; zi = ni;
            outb[i*128 + k]      = zr;   // C
            outb[i*128 + 64 + k] = zi;   // S
        }
    }
}

extern "C" void kernel_launch(void* const* d_in, const int* in_sizes, int n_in,
                              void* d_out, int out_size)
{
    const float* x          = (const float*)d_in[0];
    const float* dt         = (const float*)d_in[1];
    const float* alpha_mod  = (const float*)d_in[2];
    const float* omega_mod  = (const float*)d_in[3];
    const float* tau_mod    = (const float*)d_in[4];
    const float* s_real_raw = (const float*)d_in[5];
    const float* s_imag     = (const float*)d_in[6];
    const float* tau_raw    = (const float*)d_in[7];
    const float* W          = (const float*)d_in[8];
    const float* bvec       = (const float*)d_in[9];
    float* out = (float*)d_out;

    cudaFuncSetAttribute(k_fused, cudaFuncAttributeMaxDynamicSharedMemorySize, 101376);

    k_init<<<1, 512>>>();
    k_fused<<<NBLK + 1, NTH, 101376>>>(x, dt, alpha_mod, omega_mod, tau_mod,
                                       bvec, W, s_real_raw, s_imag, tau_raw, out);
}

// round 8
// speedup vs baseline: 1.3323x; 1.3323x over previous
#include <cuda_runtime.h>
#include <math.h>
#include <stdint.h>

#define Tt 8192
#define Kk 64
#define NBLK 512            // pipeline blocks
#define TPB 128             // timesteps per block
#define SEQB 64             // pipeline blocks per sequence
#define NSEQ 8
#define NTH 256

// ---- device scratch (static; no runtime alloc allowed) ----
__device__ float4 g_agg[NBLK*Kk];      // per-block aggregate (Ar,Ai,Zr,Zi), layout [lin][k]
__device__ int    g_bst[NBLK];         // aggregate-published flags
__device__ int    g_sflag;             // sigma ready
__device__ float  g_sigma_inv;

__device__ __forceinline__ float softplusf(float x){
    return (x > 20.f) ? x : log1pf(expf(x));
}

// -------- init: reset flags (runs every launch; graph-safe) ----------------
__global__ void k_init()
{
    int t = threadIdx.x;
    if (t < NBLK) g_bst[t] = 0;
    if (t == 0)   g_sflag = 0;
}

// ============================ fused kernel ==================================
// block 0: sigma (Gram -> 5 squarings -> 6 power iters -> Rayleigh)
// blocks 1..512: GEMM + pointwise + chunked scan (parallel lookback) + output
__global__ void __launch_bounds__(NTH, 2)
k_fused(const float* __restrict__ x,
        const float* __restrict__ dt,
        const float* __restrict__ alpha_mod,
        const float* __restrict__ omega_mod,
        const float* __restrict__ tau_mod,
        const float* __restrict__ bvec,
        const float* __restrict__ W,
        const float* __restrict__ s_real_raw,
        const float* __restrict__ s_imag,
        const float* __restrict__ tau_raw,
        float* __restrict__ out)
{
    extern __shared__ float sm[];
    int tid = threadIdx.x;   // 256

    if (blockIdx.x == 0) {
        // ------------------------- sigma block ------------------------------
        float* sW = sm;               // 64 x 132
        float* M  = sm + 64*132;      // 64 x 68
        float* H  = sm + 64*132 + 64*68;
        __shared__ float vbuf[2][64];
        __shared__ float red[64];
        __shared__ float red2[64];

        const float4* W4 = (const float4*)W;
        #pragma unroll
        for (int r = 0; r < 8; ++r) {
            int lin = tid + r*256;
            int k = lin >> 5, d4 = lin & 31;
            ((float4*)&sW[k*132])[d4] = W4[lin];
        }
        __syncthreads();

        int ti = tid >> 4, tj = tid & 15;
        {   // Gram: M = W W^T
            float acc[4][4];
            #pragma unroll
            for (int a=0;a<4;a++){
                #pragma unroll
                for (int b2=0;b2<4;b2++) acc[a][b2]=0.f;
            }
            #pragma unroll 4
            for (int d4 = 0; d4 < 32; ++d4) {
                float4 av[4], bv[4];
                #pragma unroll
                for (int a=0;a<4;a++)  av[a] = ((const float4*)&sW[(ti*4+a)*132])[d4];
                #pragma unroll
                for (int b2=0;b2<4;b2++) bv[b2] = ((const float4*)&sW[(tj*4+b2)*132])[d4];
                #pragma unroll
                for (int a=0;a<4;a++){
                    #pragma unroll
                    for (int b2=0;b2<4;b2++){
                        acc[a][b2] += av[a].x*bv[b2].x + av[a].y*bv[b2].y
                                    + av[a].z*bv[b2].z + av[a].w*bv[b2].w;
                    }
                }
            }
            #pragma unroll
            for (int a=0;a<4;a++){
                #pragma unroll
                for (int b2=0;b2<4;b2++)
                    M[(ti*4+a)*68 + (tj*4+b2)] = acc[a][b2];
            }
        }
        __syncthreads();

        float* cur = M; float* oth = H;
        for (int sq = 0; sq < 5; ++sq) {     // G^32 (trace-normalized)
            float acc[4][4];
            #pragma unroll
            for (int a=0;a<4;a++){
                #pragma unroll
                for (int b2=0;b2<4;b2++) acc[a][b2]=0.f;
            }
            #pragma unroll 4
            for (int l = 0; l < 64; ++l) {
                float a0 = cur[(ti*4+0)*68 + l];
                float a1 = cur[(ti*4+1)*68 + l];
                float a2 = cur[(ti*4+2)*68 + l];
                float a3 = cur[(ti*4+3)*68 + l];
                float4 bv = *(const float4*)&cur[l*68 + tj*4];
                acc[0][0]+=a0*bv.x; acc[0][1]+=a0*bv.y; acc[0][2]+=a0*bv.z; acc[0][3]+=a0*bv.w;
                acc[1][0]+=a1*bv.x; acc[1][1]+=a1*bv.y; acc[1][2]+=a1*bv.z; acc[1][3]+=a1*bv.w;
                acc[2][0]+=a2*bv.x; acc[2][1]+=a2*bv.y; acc[2][2]+=a2*bv.z; acc[2][3]+=a2*bv.w;
                acc[3][0]+=a3*bv.x; acc[3][1]+=a3*bv.y; acc[3][2]+=a3*bv.z; acc[3][3]+=a3*bv.w;
            }
            #pragma unroll
            for (int a=0;a<4;a++){
                #pragma unroll
                for (int b2=0;b2<4;b2++)
                    oth[(ti*4+a)*68 + tj*4+b2] = acc[a][b2];
            }
            __syncthreads();
            if (tid < 64) red[tid] = oth[tid*68 + tid];
            __syncthreads();
            for (int s = 32; s > 0; s >>= 1) {
                if (tid < s) red[tid] += red[tid+s];
                __syncthreads();
            }
            float sc = 1.0f / red[0];
            #pragma unroll
            for (int r = 0; r < 16; ++r) {
                int lin = tid + r*256;
                oth[(lin>>6)*68 + (lin&63)] *= sc;
            }
            __syncthreads();
            float* t = cur; cur = oth; oth = t;
        }
        if (tid < 64) vbuf[0][tid] = 1.0f + 0.001f*(float)tid;
        __syncthreads();
        int i = tid >> 2, p4 = tid & 3;
        for (int it = 0; it < 6; ++it) {
            const float* v = vbuf[it & 1];
            float s = 0.f;
            #pragma unroll
            for (int l4 = 0; l4 < 4; ++l4) {
                int lb = p4*16 + l4*4;
                float4 m = *(const float4*)&cur[i*68 + lb];
                s += m.x*v[lb] + m.y*v[lb+1] + m.z*v[lb+2] + m.w*v[lb+3];
            }
            s += __shfl_xor_sync(0xffffffffu, s, 1);
            s += __shfl_xor_sync(0xffffffffu, s, 2);
            if (p4 == 0) vbuf[(it+1)&1][i] = s;
            __syncthreads();
            if (it == 3) {
                float* vn = vbuf[(it+1)&1];
                if (tid < 64) red[tid] = vn[tid]*vn[tid];
                __syncthreads();
                for (int st = 32; st > 0; st >>= 1) {
                    if (tid < st) red[tid] += red[tid+st];
                    __syncthreads();
                }
                float scl = rsqrtf(red[0]);
                if (tid < 64) vn[tid] *= scl;
                __syncthreads();
            }
        }
        const float* vf = vbuf[0];   // after 6 iters result is in vbuf[0]
        float* tvec = oth;
        if (tid < 128) {
            float s = 0.f;
            #pragma unroll 4
            for (int kk = 0; kk < 64; ++kk) s += sW[kk*132 + tid] * vf[kk];
            tvec[tid] = s;
        }
        __syncthreads();
        if (tid < 64) {
            float s = 0.f;
            #pragma unroll 4
            for (int d = 0; d < 128; ++d) s += sW[tid*132 + d] * tvec[d];
            red[tid]  = s * vf[tid];
            red2[tid] = vf[tid]*vf[tid];
        }
        __syncthreads();
        for (int st = 32; st > 0; st >>= 1) {
            if (tid < st) { red[tid] += red[tid+st]; red2[tid] += red2[tid+st]; }
            __syncthreads();
        }
        if (tid == 0) {
            g_sigma_inv = rsqrtf(red[0] / red2[0]);
            __threadfence();
            atomicExch(&g_sflag, 1);
        }
        return;
    }

    // ------------------------- pipeline blocks ------------------------------
    __shared__ float4 sSum[4*64];
    __shared__ float2 sPre[64];
    __shared__ float  sA0[64];
    __shared__ float  sO0[64];

    int lin = blockIdx.x - 1;         // 0..511
    int p   = lin & (SEQB-1);
    int bt0 = lin * TPB;

    float* xs = sm;                   // 128 rows x stride 132
    float* ws = sm + 128*132;         // 64 rows x stride 132 (raw W)

    const float4* Wg4 = (const float4*)W;
    #pragma unroll
    for (int r = 0; r < 8; ++r) {
        int l = tid + r*256;
        int k2 = l >> 5, d4 = l & 31;
        ((float4*)&ws[k2*132])[d4] = Wg4[l];
    }
    const float4* xg4 = (const float4*)x + (size_t)bt0*32;
    #pragma unroll
    for (int r = 0; r < 16; ++r) {
        int l = tid + r*256;
        int i2 = l >> 5, d4 = l & 31;
        ((float4*)&xs[i2*132])[d4] = xg4[l];
    }
    __syncthreads();

    // --- fp32 GEMM: 256 threads, 4 rows x 8 cols each ---
    int kq = tid & 7, bq = tid >> 3;
    float acc[4][8];
    #pragma unroll
    for (int a=0;a<4;a++){
        #pragma unroll
        for (int j=0;j<8;j++) acc[a][j]=0.f;
    }
    #pragma unroll 4
    for (int d4 = 0; d4 < 32; ++d4) {
        float4 xa[4], wb[8];
        #pragma unroll
        for (int a=0;a<4;a++) xa[a] = ((const float4*)&xs[(bq*4+a)*132])[d4];
        #pragma unroll
        for (int j=0;j<8;j++) wb[j] = ((const float4*)&ws[(kq+8*j)*132])[d4];
        #pragma unroll
        for (int a=0;a<4;a++){
            #pragma unroll
            for (int j=0;j<8;j++){
                acc[a][j] += xa[a].x*wb[j].x + xa[a].y*wb[j].y
                           + xa[a].z*wb[j].z + xa[a].w*wb[j].w;
            }
        }
    }

    // alpha0/omega0 per block (64 softplus, not 4096)
    if (tid < 64) {
        float tauv = softplusf(tau_raw[0]) + 1e-3f;
        sA0[tid] = (softplusf(s_real_raw[tid]) + 1e-6f) * tauv;
        sO0[tid] = s_imag[tid] * tauv;
    }
    __syncthreads();   // tiles consumed; reuse as a/u stage

    float* sAr = sm;                  // [128][65]
    float* sAi = sm + 128*65;
    float* sU  = sm + 2*128*65;

    // --- epilogue: a_t via tiny-arg Taylor; store RAW acc (sigma applied later) ---
    #pragma unroll
    for (int a = 0; a < 4; ++a) {
        int tl = bq*4 + a;
        int bt = bt0 + tl;
        float dtv = dt[bt];
        float tm  = tau_mod[bt];
        #pragma unroll
        for (int j = 0; j < 8; ++j) {
            int k2 = kq + 8*j;
            int idx = bt*64 + k2;
            float ad = sA0[k2] * __expf(alpha_mod[idx] + tm) * dtv;
            float th = sO0[k2] * __expf(omega_mod[idx] + tm) * dtv;
            float rho = 1.f - ad*(1.f - ad*(0.5f - 0.16666667f*ad));
            float t2  = th*th;
            float cs  = 1.f - 0.5f*t2*(1.f - 0.083333336f*t2);
            float sn  = th*(1.f - 0.16666667f*t2);
            sAr[tl*65 + k2] = rho*cs;
            sAi[tl*65 + k2] = rho*sn;
            sU [tl*65 + k2] = acc[a][j];
        }
    }

    // --- wait for sigma (overlapped by GEMM + epilogue) ---
    if (tid == 0) {
        while (atomicAdd(&g_sflag, 0) == 0) __nanosleep(100);
    }
    __syncthreads();
    __threadfence();
    float siginv = *(volatile float*)&g_sigma_inv;

    int cc = tid >> 6, k = tid & 63;  // 4 sub-chunks x 64 lanes
    float bk = bvec[k];

    // --- local sub-chunk scans: 4 x 32 steps ---
    {
        int tb = cc*32;
        float zr=0.f, zi=0.f, Ar=1.f, Ai=0.f;
        #pragma unroll 8
        for (int i = 0; i < 32; ++i) {
            float ar = sAr[(tb+i)*65 + k];
            float ai = sAi[(tb+i)*65 + k];
            float u  = siginv*sU[(tb+i)*65 + k] + bk;
            float nr = ar*zr - ai*zi + u;
            float ni = ai*zr + ar*zi;
            zr = nr; zi = ni;
            float br = ar*Ar - ai*Ai;
            float bi = ai*Ar + ar*Ai;
            Ar = br; Ai = bi;
        }
        sSum[cc*64 + k] = make_float4(Ar, Ai, zr, zi);
    }
    __syncthreads();

    // --- block aggregate (lanes 0..63), publish agg + flag ---
    if (tid < 64) {
        float bAr=1.f, bAi=0.f, bZr=0.f, bZi=0.f;
        #pragma unroll
        for (int j = 0; j < 4; ++j) {
            float4 s4 = sSum[j*64 + tid];
            float nzr = s4.x*bZr - s4.y*bZi + s4.z;
            float nzi = s4.y*bZr + s4.x*bZi + s4.w;
            float nar = s4.x*bAr - s4.y*bAi;
            float nai = s4.y*bAr + s4.x*bAi;
            bZr=nzr; bZi=nzi; bAr=nar; bAi=nai;
        }
        g_agg[lin*Kk + tid] = make_float4(bAr, bAi, bZr, bZi);
        __threadfence();
    }
    __syncthreads();
    if (tid == 0) atomicExch(&g_bst[lin], 1);

    // --- parallel lookback: wait for all p predecessor flags, then fold ---
    float pr = 0.f, pi = 0.f;
    if (p > 0) {
        if (tid < p) {
            while (atomicAdd(&g_bst[lin - 1 - tid], 0) == 0) __nanosleep(60);
        }
        __syncthreads();
        __threadfence();
        if (tid < 64) {
            // fold predecessors newest -> oldest with batched independent loads
            float Ra=1.f, Rb=0.f, Rzr=0.f, Rzi=0.f;
            int w = lin - 1;
            int wend = lin - p;               // sequence start
            while (w >= wend) {
                int nb = w - wend + 1; if (nb > 8) nb = 8;
                float4 ag[8];
                #pragma unroll
                for (int b = 0; b < 8; ++b) {
                    if (b < nb) ag[b] = __ldcg(&g_agg[(w - b)*Kk + tid]);
                }
                #pragma unroll
                for (int b = 0; b < 8; ++b) {
                    if (b < nb) {
                        float4 A = ag[b];
                        float nzr = Ra*A.z - Rb*A.w + Rzr;
                        float nzi = Rb*A.z + Ra*A.w + Rzi;
                        float nar = Ra*A.x - Rb*A.y;
                        float nai = Ra*A.y + Rb*A.x;
                        Rzr=nzr; Rzi=nzi; Ra=nar; Rb=nai;
                    }
                }
                w -= nb;
            }
            pr = Rzr; pi = Rzi;
        }
    }

    if (tid < 64) sPre[tid] = make_float2(pr, pi);
    __syncthreads();

    // --- final scan with correct init, write output ---
    {
        float2 z0 = sPre[k];
        float zr = z0.x, zi = z0.y;
        #pragma unroll
        for (int j = 0; j < 3; ++j) {
            if (j < cc) {
                float4 s4 = sSum[j*64 + k];
                float nr = s4.x*zr - s4.y*zi + s4.z;
                float ni = s4.y*zr + s4.x*zi + s4.w;
                zr = nr; zi = ni;
            }
        }
        int tb = cc*32;
        float* outb = out + (size_t)(bt0 + tb)*128;
        #pragma unroll 8
        for (int i = 0; i < 32; ++i) {
            float ar = sAr[(tb+i)*65 + k];
            float ai = sAi[(tb+i)*65 + k];
            float u  = siginv*sU[(tb+i)*65 + k] + bk;
            float nr = ar*zr - ai*zi + u;
            float ni = ai*zr + ar*zi;
            zr = nr; zi = ni;
            outb[i*128 + k]      = zr;   // C
            outb[i*128 + 64 + k] = zi;   // S
        }
    }
}

extern "C" void kernel_launch(void* const* d_in, const int* in_sizes, int n_in,
                              void* d_out, int out_size)
{
    const float* x          = (const float*)d_in[0];
    const float* dt         = (const float*)d_in[1];
    const float* alpha_mod  = (const float*)d_in[2];
    const float* omega_mod  = (const float*)d_in[3];
    const float* tau_mod    = (const float*)d_in[4];
    const float* s_real_raw = (const float*)d_in[5];
    const float* s_imag     = (const float*)d_in[6];
    const float* tau_raw    = (const float*)d_in[7];
    const float* W          = (const float*)d_in[8];
    const float* bvec       = (const float*)d_in[9];
    float* out = (float*)d_out;

    cudaFuncSetAttribute(k_fused, cudaFuncAttributeMaxDynamicSharedMemorySize, 101376);

    k_init<<<1, 512>>>();
    k_fused<<<NBLK + 1, NTH, 101376>>>(x, dt, alpha_mod, omega_mod, tau_mod,
                                       bvec, W, s_real_raw, s_imag, tau_raw, out);
}

// round 9
// speedup vs baseline: 1.3648x; 1.0244x over previous
#include <cuda_runtime.h>
#include <math.h>
#include <stdint.h>

#define Tt 8192
#define Kk 64
#define NBLK 512            // pipeline blocks
#define TPB 128             // timesteps per block
#define SEQB 64             // pipeline blocks per sequence
#define NTH 256

// ---- device scratch (static; no runtime alloc allowed) ----
__device__ float4 g_agg[NBLK*Kk];      // per-block aggregate (Ar,Ai,Zr,Zi), layout [lin][k]
__device__ int    g_bst[NBLK];         // aggregate-published flags
__device__ int    g_sflag;             // sigma ready
__device__ float  g_sigma_inv;

__device__ __forceinline__ float softplusf(float x){
    return (x > 20.f) ? x : log1pf(expf(x));
}

// packed f32x2 helpers (base sm_100+ PTX; NOT family-'a'-gated)
__device__ __forceinline__ void fma_x2(unsigned long long& d,
                                       unsigned long long a,
                                       unsigned long long b){
    asm("fma.rn.f32x2 %0, %1, %2, %3;" : "=l"(d) : "l"(a), "l"(b), "l"(d));
}
__device__ __forceinline__ unsigned long long bcast_x2(float x){
    unsigned long long r;
    asm("mov.b64 %0, {%1, %1};" : "=l"(r) : "f"(x));
    return r;
}

// -------- init: reset flags (runs every launch; graph-safe) ----------------
__global__ void k_init()
{
    int t = threadIdx.x;
    if (t < NBLK) g_bst[t] = 0;
    if (t == 0)   g_sflag = 0;
}

// ============================ fused kernel ==================================
// block 0: sigma (Gram -> 5 squarings -> 6 power iters -> Rayleigh)
// blocks 1..512: GEMM(f32x2) + pointwise + chunked scan (parallel lookback) + out
__global__ void __launch_bounds__(NTH, 2)
k_fused(const float* __restrict__ x,
        const float* __restrict__ dt,
        const float* __restrict__ alpha_mod,
        const float* __restrict__ omega_mod,
        const float* __restrict__ tau_mod,
        const float* __restrict__ bvec,
        const float* __restrict__ W,
        const float* __restrict__ s_real_raw,
        const float* __restrict__ s_imag,
        const float* __restrict__ tau_raw,
        float* __restrict__ out)
{
    extern __shared__ float sm[];
    int tid = threadIdx.x;   // 256

    if (blockIdx.x == 0) {
        // ------------------------- sigma block ------------------------------
        float* sW = sm;               // 64 x 132
        float* M  = sm + 64*132;      // 64 x 68
        float* H  = sm + 64*132 + 64*68;
        __shared__ float vbuf[2][64];
        __shared__ float red[64];
        __shared__ float red2[64];

        const float4* W4 = (const float4*)W;
        #pragma unroll
        for (int r = 0; r < 8; ++r) {
            int lin = tid + r*256;
            int k = lin >> 5, d4 = lin & 31;
            ((float4*)&sW[k*132])[d4] = W4[lin];
        }
        __syncthreads();

        int ti = tid >> 4, tj = tid & 15;
        {   // Gram: M = W W^T
            float acc[4][4];
            #pragma unroll
            for (int a=0;a<4;a++){
                #pragma unroll
                for (int b2=0;b2<4;b2++) acc[a][b2]=0.f;
            }
            #pragma unroll 4
            for (int d4 = 0; d4 < 32; ++d4) {
                float4 av[4], bv[4];
                #pragma unroll
                for (int a=0;a<4;a++)  av[a] = ((const float4*)&sW[(ti*4+a)*132])[d4];
                #pragma unroll
                for (int b2=0;b2<4;b2++) bv[b2] = ((const float4*)&sW[(tj*4+b2)*132])[d4];
                #pragma unroll
                for (int a=0;a<4;a++){
                    #pragma unroll
                    for (int b2=0;b2<4;b2++){
                        acc[a][b2] += av[a].x*bv[b2].x + av[a].y*bv[b2].y
                                    + av[a].z*bv[b2].z + av[a].w*bv[b2].w;
                    }
                }
            }
            #pragma unroll
            for (int a=0;a<4;a++){
                #pragma unroll
                for (int b2=0;b2<4;b2++)
                    M[(ti*4+a)*68 + (tj*4+b2)] = acc[a][b2];
            }
        }
        __syncthreads();

        float* cur = M; float* oth = H;
        for (int sq = 0; sq < 5; ++sq) {     // G^32 (trace-normalized)
            float acc[4][4];
            #pragma unroll
            for (int a=0;a<4;a++){
                #pragma unroll
                for (int b2=0;b2<4;b2++) acc[a][b2]=0.f;
            }
            #pragma unroll 4
            for (int l = 0; l < 64; ++l) {
                float a0 = cur[(ti*4+0)*68 + l];
                float a1 = cur[(ti*4+1)*68 + l];
                float a2 = cur[(ti*4+2)*68 + l];
                float a3 = cur[(ti*4+3)*68 + l];
                float4 bv = *(const float4*)&cur[l*68 + tj*4];
                acc[0][0]+=a0*bv.x; acc[0][1]+=a0*bv.y; acc[0][2]+=a0*bv.z; acc[0][3]+=a0*bv.w;
                acc[1][0]+=a1*bv.x; acc[1][1]+=a1*bv.y; acc[1][2]+=a1*bv.z; acc[1][3]+=a1*bv.w;
                acc[2][0]+=a2*bv.x; acc[2][1]+=a2*bv.y; acc[2][2]+=a2*bv.z; acc[2][3]+=a2*bv.w;
                acc[3][0]+=a3*bv.x; acc[3][1]+=a3*bv.y; acc[3][2]+=a3*bv.z; acc[3][3]+=a3*bv.w;
            }
            #pragma unroll
            for (int a=0;a<4;a++){
                #pragma unroll
                for (int b2=0;b2<4;b2++)
                    oth[(ti*4+a)*68 + tj*4+b2] = acc[a][b2];
            }
            __syncthreads();
            if (tid < 64) red[tid] = oth[tid*68 + tid];
            __syncthreads();
            for (int s = 32; s > 0; s >>= 1) {
                if (tid < s) red[tid] += red[tid+s];
                __syncthreads();
            }
            float sc = 1.0f / red[0];
            #pragma unroll
            for (int r = 0; r < 16; ++r) {
                int lin = tid + r*256;
                oth[(lin>>6)*68 + (lin&63)] *= sc;
            }
            __syncthreads();
            float* t = cur; cur = oth; oth = t;
        }
        if (tid < 64) vbuf[0][tid] = 1.0f + 0.001f*(float)tid;
        __syncthreads();
        int i = tid >> 2, p4 = tid & 3;
        for (int it = 0; it < 6; ++it) {
            const float* v = vbuf[it & 1];
            float s = 0.f;
            #pragma unroll
            for (int l4 = 0; l4 < 4; ++l4) {
                int lb = p4*16 + l4*4;
                float4 m = *(const float4*)&cur[i*68 + lb];
                s += m.x*v[lb] + m.y*v[lb+1] + m.z*v[lb+2] + m.w*v[lb+3];
            }
            s += __shfl_xor_sync(0xffffffffu, s, 1);
            s += __shfl_xor_sync(0xffffffffu, s, 2);
            if (p4 == 0) vbuf[(it+1)&1][i] = s;
            __syncthreads();
            if (it == 3) {
                float* vn = vbuf[(it+1)&1];
                if (tid < 64) red[tid] = vn[tid]*vn[tid];
                __syncthreads();
                for (int st = 32; st > 0; st >>= 1) {
                    if (tid < st) red[tid] += red[tid+st];
                    __syncthreads();
                }
                float scl = rsqrtf(red[0]);
                if (tid < 64) vn[tid] *= scl;
                __syncthreads();
            }
        }
        const float* vf = vbuf[0];
        float* tvec = oth;
        if (tid < 128) {
            float s = 0.f;
            #pragma unroll 4
            for (int kk = 0; kk < 64; ++kk) s += sW[kk*132 + tid] * vf[kk];
            tvec[tid] = s;
        }
        __syncthreads();
        if (tid < 64) {
            float s = 0.f;
            #pragma unroll 4
            for (int d = 0; d < 128; ++d) s += sW[tid*132 + d] * tvec[d];
            red[tid]  = s * vf[tid];
            red2[tid] = vf[tid]*vf[tid];
        }
        __syncthreads();
        for (int st = 32; st > 0; st >>= 1) {
            if (tid < st) { red[tid] += red[tid+st]; red2[tid] += red2[tid+st]; }
            __syncthreads();
        }
        if (tid == 0) {
            g_sigma_inv = rsqrtf(red[0] / red2[0]);
            __threadfence();
            atomicExch(&g_sflag, 1);
        }
        return;
    }

    // ------------------------- pipeline blocks ------------------------------
    __shared__ float4 sSum[4*64];
    __shared__ float2 sPre[64];
    __shared__ float  sA0[64];
    __shared__ float  sO0[64];

    int lin = blockIdx.x - 1;         // 0..511
    int p   = lin & (SEQB-1);
    int bt0 = lin * TPB;

    float* xs  = sm;                  // 128 rows x stride 132 floats (67584B)
    float* ws2 = sm + 128*132;        // packed W: 32 rows x 260 floats (33280B)
    // ws2 row r = jp*8+kq holds f32x2 pairs {W[kq+16jp][d], W[kq+16jp+8][d]}
    // at float offset r*260 + d*2 (+1 for the odd k).  260 floats = 1040B row
    // stride -> 8 kq-rows land on disjoint 16B bank groups for LDS.128.

    const float4* Wg4 = (const float4*)W;
    #pragma unroll
    for (int r = 0; r < 8; ++r) {
        int l = tid + r*256;          // 2048 float4s
        int k2 = l >> 5, d4 = l & 31; // W row, d4 block
        float4 w = Wg4[l];
        int kq = k2 & 7, jg = k2 >> 3;
        int jp = jg >> 1, half = jg & 1;
        float* dst = ws2 + (jp*8 + kq)*260 + (d4*4)*2 + half;
        dst[0] = w.x; dst[2] = w.y; dst[4] = w.z; dst[6] = w.w;
    }
    const float4* xg4 = (const float4*)x + (size_t)bt0*32;
    #pragma unroll
    for (int r = 0; r < 16; ++r) {
        int l = tid + r*256;
        int i2 = l >> 5, d4 = l & 31;
        ((float4*)&xs[i2*132])[d4] = xg4[l];
    }
    __syncthreads();

    // --- packed-f32x2 GEMM: 256 threads, 4 rows x 8 cols each ---
    int kq = tid & 7, bq = tid >> 3;
    unsigned long long acc2[4][4];    // [a][jp], lanes = (j=2jp, j=2jp+1)
    #pragma unroll
    for (int a=0;a<4;a++){
        #pragma unroll
        for (int jp=0;jp<4;jp++) acc2[a][jp] = 0ull;
    }
    #pragma unroll 4
    for (int d4 = 0; d4 < 32; ++d4) {
        float4 xa[4];
        #pragma unroll
        for (int a=0;a<4;a++) xa[a] = ((const float4*)&xs[(bq*4+a)*132])[d4];
        ulonglong2 wp01[4], wp23[4];  // [jp]: comps {0,1} and {2,3}
        #pragma unroll
        for (int jp=0;jp<4;jp++) {
            const float* wrow = ws2 + (jp*8 + kq)*260 + d4*8;
            wp01[jp] = *(const ulonglong2*)(wrow);
            wp23[jp] = *(const ulonglong2*)(wrow + 4);
        }
        #pragma unroll
        for (int a=0;a<4;a++){
            unsigned long long xx = bcast_x2(xa[a].x);
            unsigned long long xy = bcast_x2(xa[a].y);
            unsigned long long xz = bcast_x2(xa[a].z);
            unsigned long long xw = bcast_x2(xa[a].w);
            #pragma unroll
            for (int jp=0;jp<4;jp++){
                fma_x2(acc2[a][jp], xx, wp01[jp].x);
                fma_x2(acc2[a][jp], xy, wp01[jp].y);
                fma_x2(acc2[a][jp], xz, wp23[jp].x);
                fma_x2(acc2[a][jp], xw, wp23[jp].y);
            }
        }
    }

    // alpha0/omega0 per block (64 softplus, not 4096)
    if (tid < 64) {
        float tauv = softplusf(tau_raw[0]) + 1e-3f;
        sA0[tid] = (softplusf(s_real_raw[tid]) + 1e-6f) * tauv;
        sO0[tid] = s_imag[tid] * tauv;
    }
    __syncthreads();   // tiles consumed; reuse as a/u stage

    float* sAr = sm;                  // [128][65]
    float* sAi = sm + 128*65;
    float* sU  = sm + 2*128*65;

    // --- epilogue: a_t via tiny-arg Taylor; store RAW acc (sigma applied later) ---
    #pragma unroll
    for (int a = 0; a < 4; ++a) {
        int tl = bq*4 + a;
        int bt = bt0 + tl;
        float dtv = dt[bt];
        float tm  = tau_mod[bt];
        #pragma unroll
        for (int j = 0; j < 8; ++j) {
            int k2 = kq + 8*j;
            int idx = bt*64 + k2;
            unsigned long long pair = acc2[a][j >> 1];
            uint32_t bits = (j & 1) ? (uint32_t)(pair >> 32) : (uint32_t)pair;
            float uraw = __uint_as_float(bits);
            float ad = sA0[k2] * __expf(alpha_mod[idx] + tm) * dtv;
            float th = sO0[k2] * __expf(omega_mod[idx] + tm) * dtv;
            float rho = 1.f - ad*(1.f - ad*(0.5f - 0.16666667f*ad));
            float t2  = th*th;
            float cs  = 1.f - 0.5f*t2*(1.f - 0.083333336f*t2);
            float sn  = th*(1.f - 0.16666667f*t2);
            sAr[tl*65 + k2] = rho*cs;
            sAi[tl*65 + k2] = rho*sn;
            sU [tl*65 + k2] = uraw;
        }
    }

    // --- wait for sigma (overlapped by GEMM + epilogue) ---
    if (tid == 0) {
        while (atomicAdd(&g_sflag, 0) == 0) __nanosleep(100);
    }
    __syncthreads();
    __threadfence();
    float siginv = *(volatile float*)&g_sigma_inv;

    int cc = tid >> 6, k = tid & 63;  // 4 sub-chunks x 64 lanes
    float bk = bvec[k];

    // --- local sub-chunk scans: 4 x 32 steps ---
    {
        int tb = cc*32;
        float zr=0.f, zi=0.f, Ar=1.f, Ai=0.f;
        #pragma unroll 8
        for (int i = 0; i < 32; ++i) {
            float ar = sAr[(tb+i)*65 + k];
            float ai = sAi[(tb+i)*65 + k];
            float u  = siginv*sU[(tb+i)*65 + k] + bk;
            float nr = ar*zr - ai*zi + u;
            float ni = ai*zr + ar*zi;
            zr = nr; zi = ni;
            float br = ar*Ar - ai*Ai;
            float bi = ai*Ar + ar*Ai;
            Ar = br; Ai = bi;
        }
        sSum[cc*64 + k] = make_float4(Ar, Ai, zr, zi);
    }
    __syncthreads();

    // --- block aggregate (lanes 0..63), publish agg + flag ---
    if (tid < 64) {
        float bAr=1.f, bAi=0.f, bZr=0.f, bZi=0.f;
        #pragma unroll
        for (int j = 0; j < 4; ++j) {
            float4 s4 = sSum[j*64 + tid];
            float nzr = s4.x*bZr - s4.y*bZi + s4.z;
            float nzi = s4.y*bZr + s4.x*bZi + s4.w;
            float nar = s4.x*bAr - s4.y*bAi;
            float nai = s4.y*bAr + s4.x*bAi;
            bZr=nzr; bZi=nzi; bAr=nar; bAi=nai;
        }
        g_agg[lin*Kk + tid] = make_float4(bAr, bAi, bZr, bZi);
        __threadfence();
    }
    __syncthreads();
    if (tid == 0) atomicExch(&g_bst[lin], 1);

    // --- parallel lookback: wait for all p predecessor flags, then fold ---
    float pr = 0.f, pi = 0.f;
    if (p > 0) {
        if (tid < p) {
            while (atomicAdd(&g_bst[lin - 1 - tid], 0) == 0) __nanosleep(60);
        }
        __syncthreads();
        __threadfence();
        if (tid < 64) {
            float Ra=1.f, Rb=0.f, Rzr=0.f, Rzi=0.f;
            int w = lin - 1;
            int wend = lin - p;               // sequence start
            while (w >= wend) {
                int nb = w - wend + 1; if (nb > 8) nb = 8;
                float4 ag[8];
                #pragma unroll
                for (int b = 0; b < 8; ++b) {
                    if (b < nb) ag[b] = __ldcg(&g_agg[(w - b)*Kk + tid]);
                }
                #pragma unroll
                for (int b = 0; b < 8; ++b) {
                    if (b < nb) {
                        float4 A = ag[b];
                        float nzr = Ra*A.z - Rb*A.w + Rzr;
                        float nzi = Rb*A.z + Ra*A.w + Rzi;
                        float nar = Ra*A.x - Rb*A.y;
                        float nai = Ra*A.y + Rb*A.x;
                        Rzr=nzr; Rzi=nzi; Ra=nar; Rb=nai;
                    }
                }
                w -= nb;
            }
            pr = Rzr; pi = Rzi;
        }
    }

    if (tid < 64) sPre[tid] = make_float2(pr, pi);
    __syncthreads();

    // --- final scan with correct init, write output ---
    {
        float2 z0 = sPre[k];
        float zr = z0.x, zi = z0.y;
        #pragma unroll
        for (int j = 0; j < 3; ++j) {
            if (j < cc) {
                float4 s4 = sSum[j*64 + k];
                float nr = s4.x*zr - s4.y*zi + s4.z;
                float ni = s4.y*zr + s4.x*zi + s4.w;
                zr = nr; zi = ni;
            }
        }
        int tb = cc*32;
        float* outb = out + (size_t)(bt0 + tb)*128;
        #pragma unroll 8
        for (int i = 0; i < 32; ++i) {
            float ar = sAr[(tb+i)*65 + k];
            float ai = sAi[(tb+i)*65 + k];
            float u  = siginv*sU[(tb+i)*65 + k] + bk;
            float nr = ar*zr - ai*zi + u;
            float ni = ai*zr + ar*zi;
            zr = nr; zi = ni;
            outb[i*128 + k]      = zr;   // C
            outb[i*128 + 64 + k] = zi;   // S
        }
    }
}

extern "C" void kernel_launch(void* const* d_in, const int* in_sizes, int n_in,
                              void* d_out, int out_size)
{
    const float* x          = (const float*)d_in[0];
    const float* dt         = (const float*)d_in[1];
    const float* alpha_mod  = (const float*)d_in[2];
    const float* omega_mod  = (const float*)d_in[3];
    const float* tau_mod    = (const float*)d_in[4];
    const float* s_real_raw = (const float*)d_in[5];
    const float* s_imag     = (const float*)d_in[6];
    const float* tau_raw    = (const float*)d_in[7];
    const float* W          = (const float*)d_in[8];
    const float* bvec       = (const float*)d_in[9];
    float* out = (float*)d_out;

    cudaFuncSetAttribute(k_fused, cudaFuncAttributeMaxDynamicSharedMemorySize, 101376);

    k_init<<<1, 512>>>();
    k_fused<<<NBLK + 1, NTH, 101376>>>(x, dt, alpha_mod, omega_mod, tau_mod,
                                       bvec, W, s_real_raw, s_imag, tau_raw, out);
}